// round 9
// baseline (speedup 1.0000x reference)
#include <cuda_runtime.h>

// out[b,t,w,c] = x[b, t+w-9, c], zero-padded in t.  B=32, T=4096, W=19, C=30.
// Identity: out row (b,t) [570 floats] == contiguous x slice starting at
// flat element (b*4096 + t - 9)*30, with pad rows zeroed.
//
// R5 champion structure (smem stage + conflict-free float2 emit), with ONE
// change: st.global.wt (write-through) instead of .cs, probing whether the
// L2 write-back/dirty-drain path is what caps sustained BW at ~6.4 TB/s.

#define T_DIM   4096
#define C_DIM   30
#define ROW     570             // W*C
#define PAD     9
#define TT      64              // t-rows per block
#define SROWS   (TT + 2*PAD)    // 82
#define SFLOATS (SROWS * C_DIM) // 2460
#define THREADS 480
#define ITERS   38              // TT*ROW/2 / THREADS = 18240/480

__device__ __forceinline__ void stg_wt_v2(float2* p, float2 v) {
    asm volatile("st.global.wt.v2.f32 [%0], {%1,%2};"
                 :: "l"(p), "f"(v.x), "f"(v.y) : "memory");
}

__global__ __launch_bounds__(THREADS)
void overlap_window_smem_wt_kernel(const float* __restrict__ x,
                                   float2* __restrict__ out2) {
    __shared__ float s[SFLOATS];

    const int tile = blockIdx.x;            // 0 .. 2047
    const int tpb  = T_DIM / TT;            // 64 tiles per batch
    const int b    = tile / tpb;
    const int t0   = (tile - b * tpb) * TT;
    const int tid  = threadIdx.x;

    // ---- stage x[(b*4096 + t0 - 9)*30 ... +2460) into smem, zeroing pad ----
    const int lo = (t0 == 0) ? (PAD * C_DIM) : 0;
    const int hi_raw = (T_DIM - t0 + PAD) * C_DIM;
    const int hi = hi_raw < SFLOATS ? hi_raw : SFLOATS;
    const int gbase = (b * T_DIM + t0 - PAD) * C_DIM;  // even
    const float2* __restrict__ x2 = (const float2*)x;
    float2* __restrict__ s2 = (float2*)s;

    #pragma unroll
    for (int k = 0; k < (SFLOATS / 2 + THREADS - 1) / THREADS; k++) {
        int idx2 = tid + k * THREADS;
        if (idx2 < SFLOATS / 2) {
            int i = idx2 * 2;
            float2 v = make_float2(0.0f, 0.0f);
            if (i >= lo && i < hi) {
                v = __ldg(&x2[(gbase >> 1) + idx2]);
            }
            s2[idx2] = v;
        }
    }
    __syncthreads();

    // ---- emit 18240 float2s; float2 index q = tid + k*480, element e = 2q ----
    float2* __restrict__ out_tile = out2 + ((size_t)(b * T_DIM + t0) * ROW) / 2;

    int e   = tid * 2;                  // 0..958
    int r   = (e >= ROW) ? 1 : 0;
    int rem = e - r * ROW;

    #pragma unroll
    for (int k = 0; k < ITERS; k++) {
        int src = r * C_DIM + rem;      // even -> 8B aligned
        float2 v = *(const float2*)&s[src];
        stg_wt_v2(&out_tile[tid + k * THREADS], v);

        rem += 960 - ROW;               // += 390
        r   += 1;
        if (rem >= ROW) { rem -= ROW; r += 1; }
    }
}

extern "C" void kernel_launch(void* const* d_in, const int* in_sizes, int n_in,
                              void* d_out, int out_size) {
    const float* x = (const float*)d_in[0];
    float2* out2 = (float2*)d_out;
    const int blocks = 32 * (T_DIM / TT);   // 2048
    overlap_window_smem_wt_kernel<<<blocks, THREADS>>>(x, out2);
}

// round 10
// speedup vs baseline: 1.1374x; 1.1374x over previous
#include <cuda_runtime.h>

// out[b,t,w,c] = x[b, t+w-9, c], zero-padded in t.  B=32, T=4096, W=19, C=30.
// Identity: out row (b,t) [570 floats] == contiguous x slice starting at
// flat element (b*4096 + t - 9)*30, with pad rows zeroed.
//
// Champion structure (R5): smem stage + conflict-free float2 emit + .cs stores.
// This round: staging via cp.async.ca with src-size zero-fill (LDGSTS) —
// removes the load->reg->STS round trip and the explicit pad-zero branch.

#define T_DIM   4096
#define C_DIM   30
#define ROW     570             // W*C
#define PAD     9
#define TT      64              // t-rows per block
#define SROWS   (TT + 2*PAD)    // 82
#define SFLOATS (SROWS * C_DIM) // 2460
#define THREADS 480
#define ITERS   38              // TT*ROW/2 / THREADS = 18240/480

__device__ __forceinline__ void stg_cs_v2(float2* p, float2 v) {
    asm volatile("st.global.cs.v2.f32 [%0], {%1,%2};"
                 :: "l"(p), "f"(v.x), "f"(v.y) : "memory");
}

// cp.async 8B with runtime src-size: src_bytes==0 -> zero-fill destination.
__device__ __forceinline__ void cp_async_8_zfill(unsigned smem_addr,
                                                 const void* gptr,
                                                 unsigned src_bytes) {
    asm volatile("cp.async.ca.shared.global [%0], [%1], 8, %2;"
                 :: "r"(smem_addr), "l"(gptr), "r"(src_bytes) : "memory");
}

__global__ __launch_bounds__(THREADS)
void overlap_window_cpasync_kernel(const float* __restrict__ x,
                                   float2* __restrict__ out2) {
    __shared__ float s[SFLOATS];

    const int tile = blockIdx.x;            // 0 .. 2047
    const int tpb  = T_DIM / TT;            // 64 tiles per batch
    const int b    = tile / tpb;
    const int t0   = (tile - b * tpb) * TT;
    const int tid  = threadIdx.x;

    // ---- stage x[(b*4096 + t0 - 9)*30 ... +2460) into smem via cp.async ----
    // smem element-pair idx2 holds x flat elements (gbase + 2*idx2, +1);
    // valid iff lo <= 2*idx2 < hi (outside -> zero-fill via src_bytes = 0).
    const int lo = (t0 == 0) ? (PAD * C_DIM) : 0;
    const int hi_raw = (T_DIM - t0 + PAD) * C_DIM;
    const int hi = hi_raw < SFLOATS ? hi_raw : SFLOATS;
    const int gbase = (b * T_DIM + t0 - PAD) * C_DIM;  // even
    const float2* __restrict__ x2 = (const float2*)x;

    unsigned s_base;
    asm("{ .reg .u64 t; cvta.to.shared.u64 t, %1; cvt.u32.u64 %0, t; }"
        : "=r"(s_base) : "l"((const void*)s));

    #pragma unroll
    for (int k = 0; k < (SFLOATS / 2 + THREADS - 1) / THREADS; k++) {
        int idx2 = tid + k * THREADS;
        if (idx2 < SFLOATS / 2) {
            int i = idx2 * 2;
            unsigned nbytes = (i >= lo && i < hi) ? 8u : 0u;
            cp_async_8_zfill(s_base + (unsigned)idx2 * 8u,
                             (const void*)&x2[(gbase >> 1) + idx2], nbytes);
        }
    }
    asm volatile("cp.async.commit_group;" ::: "memory");
    asm volatile("cp.async.wait_group 0;" ::: "memory");
    __syncthreads();

    // ---- emit 18240 float2s; float2 index q = tid + k*480, element e = 2q ----
    float2* __restrict__ out_tile = out2 + ((size_t)(b * T_DIM + t0) * ROW) / 2;

    int e   = tid * 2;                  // 0..958
    int r   = (e >= ROW) ? 1 : 0;
    int rem = e - r * ROW;

    #pragma unroll
    for (int k = 0; k < ITERS; k++) {
        int src = r * C_DIM + rem;      // even -> 8B aligned
        float2 v = *(const float2*)&s[src];
        stg_cs_v2(&out_tile[tid + k * THREADS], v);

        rem += 960 - ROW;               // += 390
        r   += 1;
        if (rem >= ROW) { rem -= ROW; r += 1; }
    }
}

extern "C" void kernel_launch(void* const* d_in, const int* in_sizes, int n_in,
                              void* d_out, int out_size) {
    const float* x = (const float*)d_in[0];
    float2* out2 = (float2*)d_out;
    const int blocks = 32 * (T_DIM / TT);   // 2048
    overlap_window_cpasync_kernel<<<blocks, THREADS>>>(x, out2);
}